// round 13
// baseline (speedup 1.0000x reference)
#include <cuda_runtime.h>
#include <math.h>

#define NM      64
#define A_DIM   8400
#define E_DIM   128
#define NHEAD   4
#define HDIM    32
#define HWSZ    25600      // 160*160
#define LN_EPS  1e-5f
#define LOG2E   1.4426950408889634f
#define TABN    8192
#define XMIN    -10.0f
#define XMAX    10.0f

#define POOL_BLOCKS 1280         // 320 float4 each, 20 blocks per module (exact)
#define POOL_TPB    256          // 256 thr x 5 f4 = 1280 f4 per block? NO: see below
// Layout: each block covers 1280 float4 (256 thr x 5). 1280 blocks x 1280 f4
// would be 1.6384M x 1.28 -> wrong. Correct: total f4 = 1,638,400.
// 1280 blocks cover 1280 f4 each = 1,638,400 exact. Each thread loads 5 f4
// strided by 256. Module = 6400 f4 = 5 blocks. Partials per module = 5... NO:
// 1,638,400 / 1280 = 1280 f4 per block -> blocks per module = 6400/1280 = 5.
// With 1280 blocks that covers 1280*1280 = 1,638,400 f4. Exact. 20 partials/module? No: 5 per
// module x 256 modules? There are 64 modules -> 1280/64 = 20 blocks/module.
// CONTRADICTION: 6400 f4 per module / 1280 f4 per block = 5 blocks/module -> 320 blocks total.
// Therefore for 1280 blocks each block must cover 1,638,400/1280 = 1280 f4. And
// 6400/1280 = 5 -> 5 blocks/module -> only 320 blocks. So 1280 blocks needs
// 320 f4/block: 256 threads x 1.25 -> invalid. USE: 256 thr x 2 f4 = 512 f4? 6400/512 not integer.
// Clean choice: 640 blocks x 256 thr, 10 f4-strided?? 640x2560=1.6384M: block covers 2560 f4,
// 6400/2560 not integer. FINAL clean choice: 800 blocks x 256 thr x 8 f4 = block covers 2048 f4;
// 6400/2048 not integer either. Use module-interleaved mapping instead: partials
// are PER-BLOCK arbitrary slices; table kernel re-reduces per module by exact
// f4-range ownership. Simplest exact scheme: 64 modules x 16 blocks = 1024 blocks,
// each block covers 400 f4 of its module (400 = 6400/16), 256 threads: t<144 load 2 f4, rest 1.
#undef POOL_BLOCKS
#undef POOL_TPB
#define POOL_BLOCKS 1024         // 16 blocks per module, 400 float4 each (exact)
#define POOL_TPB    256
#define TAB_BLOCKS  128          // 64 nodes per block, 4 threads/node -> 8192 nodes
#define TAB_TPB     256
#define APPLY_BLOCKS 350
#define APPLY_TPB    384         // 350*384 = 134400 float4 exactly

// ---------------- device scratch (no allocation allowed) ----------------
__device__ float        g_partial[POOL_BLOCKS];
__device__ float4       g_AB[NHEAD * NM];   // (A1,A2,A3,W); A* pre-scaled log2e*scale
__device__ float        g_qstat[3];         // {Vw, 2*Cwb, Vb+eps} for queries
__device__ __align__(16) float2 g_G2[TABN]; // (G[i], G[i+1]) pairs — gate folded in

__device__ __forceinline__ float fast_ex2(float x) {
    float y; asm("ex2.approx.f32 %0, %1;" : "=f"(y) : "f"(x)); return y;
}

// one head's softmax contribution: ws/se over 64 modules (r precomputed)
__device__ __forceinline__ float eval_head(float x, float r, const float4* __restrict__ ABh)
{
    float mx = -1e30f;
    #pragma unroll 8
    for (int m = 0; m < NM; m++) {
        float4 ab = ABh[m];
        float s = fmaf(r, fmaf(x, ab.x, ab.y), ab.z);
        mx = fmaxf(mx, s);
    }
    float se = 0.f, ws = 0.f;
    #pragma unroll 8
    for (int m = 0; m < NM; m++) {
        float4 ab = ABh[m];
        float s = fmaf(r, fmaf(x, ab.x, ab.y), ab.z);
        float e = fast_ex2(s - mx);
        se += e;
        ws = fmaf(e, ab.w, ws);
    }
    return __fdividef(ws, se);
}

// cold fallback for |x| > 10: full F + gate from global coeffs
__device__ __noinline__ float eval_G_cold(float x, float gw0, float gw1, float gbv, float ob)
{
    float qa = g_qstat[0], qb2 = g_qstat[1], qc = g_qstat[2];
    float r = rsqrtf(fmaf(x, fmaf(qa, x, qb2), qc));
    float F = ob;
    #pragma unroll
    for (int h = 0; h < NHEAD; h++)
        F += eval_head(x, r, g_AB + h * NM);
    float z = fmaf(gw1, F, fmaf(gw0, x, gbv));
    float g = __fdividef(1.0f, 1.0f + fast_ex2(z));
    return fmaf(g, F - x, x);
}

// =================== kernel 1: prototype pooling (high occupancy) ===================
// 1024 blocks; block covers 400 consecutive float4 of one module.
// threads 0..143 load 2 f4 (stride 256), threads 144..255 load 1 f4.
__global__ __launch_bounds__(POOL_TPB) void pool_kernel(const float* __restrict__ proto) {
    __shared__ float s_red[8];
    const int t = threadIdx.x;
    const float4* p4 = reinterpret_cast<const float4*>(proto) + (size_t)blockIdx.x * 400;
    float4 v0 = p4[t];
    const bool h2 = (t < 144);
    float4 v1 = h2 ? p4[t + 256] : make_float4(0.f, 0.f, 0.f, 0.f);
    float sum = ((v0.x + v0.y) + (v0.z + v0.w)) + ((v1.x + v1.y) + (v1.z + v1.w));
    #pragma unroll
    for (int off = 16; off; off >>= 1) sum += __shfl_down_sync(0xffffffffu, sum, off);
    if ((t & 31) == 0) s_red[t >> 5] = sum;
    __syncthreads();
    if (t == 0) {
        float v = 0.f;
        #pragma unroll
        for (int w2 = 0; w2 < 8; w2++) v += s_red[w2];
        g_partial[blockIdx.x] = v;
    }
}

// =================== kernel 2: coefficients + G-table ===================
__global__ __launch_bounds__(TAB_TPB) void table_kernel(
    const float* __restrict__ qw, const float* __restrict__ qb,
    const float* __restrict__ qg, const float* __restrict__ qbeta,
    const float* __restrict__ kw, const float* __restrict__ kb,
    const float* __restrict__ kg, const float* __restrict__ kbeta,
    const float* __restrict__ vw, const float* __restrict__ vb,
    const float* __restrict__ vg, const float* __restrict__ vbeta,
    const float* __restrict__ outw, const float* __restrict__ outb,
    const float* __restrict__ gatew, const float* __restrict__ gateb)
{
    const int tb = blockIdx.x;           // 0..127
    const int t  = threadIdx.x;
    __shared__ float  s_pooled[NM];
    __shared__ float  s_stats[15];
    __shared__ float4 s_k[E_DIM];
    __shared__ float4 s_v[E_DIM];
    __shared__ float4 s_q[E_DIM];
    __shared__ float  s_ow[E_DIM];
    __shared__ float4 sAB[NHEAD * NM];

    // stage params (E = 128)
    if (t < E_DIM) {
        s_k[t] = make_float4(kw[t], kb[t], kg[t], kbeta[t]);
        s_v[t] = make_float4(vw[t], vb[t], vg[t], vbeta[t]);
        s_q[t] = make_float4(qw[t], qb[t], qg[t], qbeta[t]);
        s_ow[t] = outw[t];
    }
    if (t >= 64 && t < 96) {             // warp 2: moment sums
        int lane = t & 31;
        float acc[15];
        #pragma unroll
        for (int i = 0; i < 15; i++) acc[i] = 0.f;
        #pragma unroll
        for (int rep = 0; rep < 4; rep++) {
            int e = lane + rep * 32;
            float a, b;
            a = qw[e]; b = qb[e];
            acc[0] += a; acc[1] += b; acc[2] += a*a; acc[3] += a*b; acc[4] += b*b;
            a = kw[e]; b = kb[e];
            acc[5] += a; acc[6] += b; acc[7] += a*a; acc[8] += a*b; acc[9] += b*b;
            a = vw[e]; b = vb[e];
            acc[10] += a; acc[11] += b; acc[12] += a*a; acc[13] += a*b; acc[14] += b*b;
        }
        #pragma unroll
        for (int off = 16; off; off >>= 1)
            #pragma unroll
            for (int i = 0; i < 15; i++) acc[i] += __shfl_down_sync(0xffffffffu, acc[i], off);
        if (lane == 0) {
            const float inv = 1.0f / (float)E_DIM;
            #pragma unroll
            for (int gi = 0; gi < 3; gi++) {
                float mw = acc[gi*5+0] * inv;
                float mb = acc[gi*5+1] * inv;
                s_stats[gi*5+0] = mw;
                s_stats[gi*5+1] = mb;
                s_stats[gi*5+2] = acc[gi*5+2] * inv - mw*mw;
                s_stats[gi*5+3] = acc[gi*5+3] * inv - mw*mb;
                s_stats[gi*5+4] = acc[gi*5+4] * inv - mb*mb;
            }
        }
    }
    if (t < NM) {
        float s = 0.f;
        #pragma unroll
        for (int j = 0; j < 16; j++) s += g_partial[t * 16 + j];
        s_pooled[t] = s * (1.0f / (float)HWSZ);
    }
    __syncthreads();

    float qa  = s_stats[2];
    float qb2 = 2.0f * s_stats[3];
    float qc  = s_stats[4] + LN_EPS;
    if (tb == 0 && t == 0) {
        g_qstat[0] = qa; g_qstat[1] = qb2; g_qstat[2] = qc;
    }

    // coefficients: thread t -> (head, module) entry t (256 exact)
    {
        float mqw = s_stats[0],  mqb = s_stats[1];
        float mkw = s_stats[5],  mkb = s_stats[6];
        float Vkw = s_stats[7],  Ckwb = s_stats[8],  Vkb = s_stats[9];
        float mvw = s_stats[10], mvb = s_stats[11];
        float Vvw = s_stats[12], Cvwb = s_stats[13], Vvb = s_stats[14];
        const float cscale = rsqrtf((float)HDIM) * LOG2E;

        int h = t >> 6, m = t & 63;
        float p = s_pooled[m];
        float rk = rsqrtf(p * p * Vkw + 2.0f * p * Ckwb + Vkb + LN_EPS);
        float rv = rsqrtf(p * p * Vvw + 2.0f * p * Cvwb + Vvb + LN_EPS);

        float a1 = 0.f, a2 = 0.f, a3 = 0.f, w = 0.f;
        #pragma unroll 8
        for (int j = 0; j < HDIM; j++) {
            int e = h * HDIM + j;
            float4 kk = s_k[e];
            float4 vv = s_v[e];
            float4 qq = s_q[e];
            float ke = ((kk.x - mkw) * p + (kk.y - mkb)) * rk * kk.z + kk.w;
            float ve = ((vv.x - mvw) * p + (vv.y - mvb)) * rv * vv.z + vv.w;
            float uq = (qq.x - mqw) * qq.z;
            float tq = (qq.y - mqb) * qq.z;
            a1 = fmaf(uq, ke, a1);
            a2 = fmaf(tq, ke, a2);
            a3 = fmaf(qq.w, ke, a3);
            w  = fmaf(ve, s_ow[e], w);
        }
        float4 out4 = make_float4(a1 * cscale, a2 * cscale, a3 * cscale, w);
        sAB[t] = out4;
        if (tb == 0) g_AB[t] = out4;
    }
    __syncthreads();

    // G-table: 4 threads/node (one head each), shfl-combine, gate folded
    const float hstep = (XMAX - XMIN) / (float)(TABN - 1);
    float ob  = outb[0];
    float gw0 = __ldg(gatew)     * -LOG2E;
    float gw1 = __ldg(gatew + 1) * -LOG2E;
    float gbv = __ldg(gateb)     * -LOG2E;
    int node = tb * 64 + (t >> 2);       // 128 blocks * 64 = 8192
    int hh   = t & 3;
    float x  = XMIN + (float)node * hstep;
    float r  = rsqrtf(fmaf(x, fmaf(qa, x, qb2), qc));
    float part = eval_head(x, r, sAB + (hh << 6));
    part += __shfl_xor_sync(0xffffffffu, part, 1);
    part += __shfl_xor_sync(0xffffffffu, part, 2);
    if (hh == 0) {
        float F = part + ob;
        float z = fmaf(gw1, F, fmaf(gw0, x, gbv));
        float g = __fdividef(1.0f, 1.0f + fast_ex2(z));
        float G = fmaf(g, F - x, x);
        g_G2[node].x = G;
        if (node > 0) g_G2[node - 1].y = G;
    }
}

// =================== kernel 3: apply (direct L2 gather, lerp only) ===================
__global__ __launch_bounds__(APPLY_TPB) void apply_kernel(
    const float* __restrict__ coeff, float* __restrict__ out,
    const float* __restrict__ gatew, const float* __restrict__ gateb,
    const float* __restrict__ outb)
{
    int tid = blockIdx.x * APPLY_TPB + threadIdx.x;   // one float4 each, exact
    const float4* cin = reinterpret_cast<const float4*>(coeff);
    float4* cout = reinterpret_cast<float4*>(out);
    float gw0 = __ldg(gatew)     * -LOG2E;
    float gw1 = __ldg(gatew + 1) * -LOG2E;
    float gbv = __ldg(gateb)     * -LOG2E;
    float ob  = __ldg(outb);

    const float INVH = (float)(TABN - 1) / (XMAX - XMIN);
    const float BIAS = -XMIN * INVH;

    float4 xv = cin[tid];
    float xin[4] = {xv.x, xv.y, xv.z, xv.w};

    // issue all 4 table gathers up front (independent -> MLP)
    float2 p[4];
    float fpos[4];
    bool inr[4];
    #pragma unroll
    for (int j = 0; j < 4; j++) {
        float x = xin[j];
        inr[j] = (x >= XMIN) && (x <= XMAX);
        float tpos = fmaf(x, INVH, BIAS);
        int q0 = __float2int_rd(tpos);
        q0 = (q0 < 0) ? 0 : ((q0 > TABN - 2) ? TABN - 2 : q0);
        fpos[j] = tpos - (float)q0;
        p[j] = g_G2[q0];
    }

    float res[4];
    #pragma unroll
    for (int j = 0; j < 4; j++) {
        float x = xin[j];
        res[j] = inr[j] ? fmaf(fpos[j], p[j].y - p[j].x, p[j].x)
                        : eval_G_cold(x, gw0, gw1, gbv, ob);
    }
    cout[tid] = make_float4(res[0], res[1], res[2], res[3]);
}

// ---------------- launch ----------------
extern "C" void kernel_launch(void* const* d_in, const int* in_sizes, int n_in,
                              void* d_out, int out_size) {
    (void)in_sizes; (void)n_in; (void)out_size;
    const float* coeff = (const float*)d_in[0];
    const float* proto = (const float*)d_in[1];
    const float* qw    = (const float*)d_in[2];
    const float* qb    = (const float*)d_in[3];
    const float* qg    = (const float*)d_in[4];
    const float* qbeta = (const float*)d_in[5];
    const float* kw    = (const float*)d_in[6];
    const float* kb    = (const float*)d_in[7];
    const float* kg    = (const float*)d_in[8];
    const float* kbeta = (const float*)d_in[9];
    const float* vw    = (const float*)d_in[10];
    const float* vb    = (const float*)d_in[11];
    const float* vg    = (const float*)d_in[12];
    const float* vbeta = (const float*)d_in[13];
    const float* outw  = (const float*)d_in[14];
    const float* outb  = (const float*)d_in[15];
    const float* gatew = (const float*)d_in[16];
    const float* gateb = (const float*)d_in[17];
    float* out = (float*)d_out;

    pool_kernel<<<POOL_BLOCKS, POOL_TPB>>>(proto);
    table_kernel<<<TAB_BLOCKS, TAB_TPB>>>(qw, qb, qg, qbeta, kw, kb, kg, kbeta,
                                          vw, vb, vg, vbeta, outw, outb,
                                          gatew, gateb);
    apply_kernel<<<APPLY_BLOCKS, APPLY_TPB>>>(coeff, out, gatew, gateb, outb);
}

// round 14
// speedup vs baseline: 1.0153x; 1.0153x over previous
#include <cuda_runtime.h>
#include <math.h>

#define NM      64
#define A_DIM   8400
#define E_DIM   128
#define NHEAD   4
#define HDIM    32
#define HWSZ    25600      // 160*160
#define LN_EPS  1e-5f
#define LOG2E   1.4426950408889634f
#define TABN    1024
#define XMIN    -10.0f
#define XMAX    10.0f

#define POOL_BLOCKS 320          // 1280 float4 each, 5 blocks per module (exact)
#define POOL_TPB    256
#define TAB_BLOCKS  16           // 64 nodes per block, 4 threads/node -> 1024 nodes
#define TAB_TPB     256
#define APPLY_BLOCKS 350
#define APPLY_TPB    384         // 350*384 = 134400 float4 exactly

// ---------------- device scratch (no allocation allowed) ----------------
__device__ float        g_partial[POOL_BLOCKS];
__device__ float4       g_AB[NHEAD * NM];   // (A1,A2,A3,W); A* pre-scaled log2e*scale
__device__ float        g_qstat[3];         // {Vw, 2*Cwb, Vb+eps} for queries
__device__ __align__(16) float2 g_G2[TABN]; // (G[i], G[i+1]) pairs — gate folded in

__device__ __forceinline__ float fast_ex2(float x) {
    float y; asm("ex2.approx.f32 %0, %1;" : "=f"(y) : "f"(x)); return y;
}

// one head's softmax contribution: ws/se over 64 modules (r precomputed)
__device__ __forceinline__ float eval_head(float x, float r, const float4* __restrict__ ABh)
{
    float mx = -1e30f;
    #pragma unroll 8
    for (int m = 0; m < NM; m++) {
        float4 ab = ABh[m];
        float s = fmaf(r, fmaf(x, ab.x, ab.y), ab.z);
        mx = fmaxf(mx, s);
    }
    float se = 0.f, ws = 0.f;
    #pragma unroll 8
    for (int m = 0; m < NM; m++) {
        float4 ab = ABh[m];
        float s = fmaf(r, fmaf(x, ab.x, ab.y), ab.z);
        float e = fast_ex2(s - mx);
        se += e;
        ws = fmaf(e, ab.w, ws);
    }
    return __fdividef(ws, se);
}

// cold fallback for |x| > 10: full F + gate from global coeffs
__device__ __noinline__ float eval_G_cold(float x, float gw0, float gw1, float gbv, float ob)
{
    float qa = g_qstat[0], qb2 = g_qstat[1], qc = g_qstat[2];
    float r = rsqrtf(fmaf(x, fmaf(qa, x, qb2), qc));
    float F = ob;
    #pragma unroll
    for (int h = 0; h < NHEAD; h++)
        F += eval_head(x, r, g_AB + h * NM);
    float z = fmaf(gw1, F, fmaf(gw0, x, gbv));
    float g = __fdividef(1.0f, 1.0f + fast_ex2(z));
    return fmaf(g, F - x, x);
}

// =================== kernel 1: prototype pooling (R5 exact shape) ===================
__global__ __launch_bounds__(POOL_TPB) void pool_kernel(const float* __restrict__ proto) {
    __shared__ float s_red[8];
    const float4* p4 = reinterpret_cast<const float4*>(proto) + (size_t)blockIdx.x * 1280;
    int t = threadIdx.x;
    float4 v0 = p4[t];
    float4 v1 = p4[t + 256];
    float4 v2 = p4[t + 512];
    float4 v3 = p4[t + 768];
    float4 v4 = p4[t + 1024];
    float s0 = (v0.x + v0.y) + (v0.z + v0.w);
    float s1 = (v1.x + v1.y) + (v1.z + v1.w);
    float s2 = (v2.x + v2.y) + (v2.z + v2.w);
    float s3 = (v3.x + v3.y) + (v3.z + v3.w);
    float s4 = (v4.x + v4.y) + (v4.z + v4.w);
    float sum = ((s0 + s1) + (s2 + s3)) + s4;
    #pragma unroll
    for (int off = 16; off; off >>= 1) sum += __shfl_down_sync(0xffffffffu, sum, off);
    if ((t & 31) == 0) s_red[t >> 5] = sum;
    __syncthreads();
    if (t == 0) {
        float v = 0.f;
        #pragma unroll
        for (int w2 = 0; w2 < 8; w2++) v += s_red[w2];
        g_partial[blockIdx.x] = v;
    }
}

// =================== kernel 2: coefficients + G-table ===================
__global__ __launch_bounds__(TAB_TPB) void table_kernel(
    const float* __restrict__ qw, const float* __restrict__ qb,
    const float* __restrict__ qg, const float* __restrict__ qbeta,
    const float* __restrict__ kw, const float* __restrict__ kb,
    const float* __restrict__ kg, const float* __restrict__ kbeta,
    const float* __restrict__ vw, const float* __restrict__ vb,
    const float* __restrict__ vg, const float* __restrict__ vbeta,
    const float* __restrict__ outw, const float* __restrict__ outb,
    const float* __restrict__ gatew, const float* __restrict__ gateb)
{
    const int tb = blockIdx.x;           // 0..15
    const int t  = threadIdx.x;
    __shared__ float  s_pooled[NM];
    __shared__ float  s_stats[15];
    __shared__ float4 s_k[E_DIM];
    __shared__ float4 s_v[E_DIM];
    __shared__ float4 s_q[E_DIM];
    __shared__ float  s_ow[E_DIM];
    __shared__ float4 sAB[NHEAD * NM];

    // stage params (E = 128)
    if (t < E_DIM) {
        s_k[t] = make_float4(kw[t], kb[t], kg[t], kbeta[t]);
        s_v[t] = make_float4(vw[t], vb[t], vg[t], vbeta[t]);
        s_q[t] = make_float4(qw[t], qb[t], qg[t], qbeta[t]);
        s_ow[t] = outw[t];
    }
    if (t >= 64 && t < 96) {             // warp 2: moment sums
        int lane = t & 31;
        float acc[15];
        #pragma unroll
        for (int i = 0; i < 15; i++) acc[i] = 0.f;
        #pragma unroll
        for (int rep = 0; rep < 4; rep++) {
            int e = lane + rep * 32;
            float a, b;
            a = qw[e]; b = qb[e];
            acc[0] += a; acc[1] += b; acc[2] += a*a; acc[3] += a*b; acc[4] += b*b;
            a = kw[e]; b = kb[e];
            acc[5] += a; acc[6] += b; acc[7] += a*a; acc[8] += a*b; acc[9] += b*b;
            a = vw[e]; b = vb[e];
            acc[10] += a; acc[11] += b; acc[12] += a*a; acc[13] += a*b; acc[14] += b*b;
        }
        #pragma unroll
        for (int off = 16; off; off >>= 1)
            #pragma unroll
            for (int i = 0; i < 15; i++) acc[i] += __shfl_down_sync(0xffffffffu, acc[i], off);
        if (lane == 0) {
            const float inv = 1.0f / (float)E_DIM;
            #pragma unroll
            for (int gi = 0; gi < 3; gi++) {
                float mw = acc[gi*5+0] * inv;
                float mb = acc[gi*5+1] * inv;
                s_stats[gi*5+0] = mw;
                s_stats[gi*5+1] = mb;
                s_stats[gi*5+2] = acc[gi*5+2] * inv - mw*mw;
                s_stats[gi*5+3] = acc[gi*5+3] * inv - mw*mb;
                s_stats[gi*5+4] = acc[gi*5+4] * inv - mb*mb;
            }
        }
    }
    if (t < NM) {
        float s = 0.f;
        #pragma unroll
        for (int j = 0; j < 5; j++) s += g_partial[t * 5 + j];
        s_pooled[t] = s * (1.0f / (float)HWSZ);
    }
    __syncthreads();

    float qa  = s_stats[2];
    float qb2 = 2.0f * s_stats[3];
    float qc  = s_stats[4] + LN_EPS;
    if (tb == 0 && t == 0) {
        g_qstat[0] = qa; g_qstat[1] = qb2; g_qstat[2] = qc;
    }

    // coefficients: thread t -> (head, module) entry t (256 exact)
    {
        float mqw = s_stats[0],  mqb = s_stats[1];
        float mkw = s_stats[5],  mkb = s_stats[6];
        float Vkw = s_stats[7],  Ckwb = s_stats[8],  Vkb = s_stats[9];
        float mvw = s_stats[10], mvb = s_stats[11];
        float Vvw = s_stats[12], Cvwb = s_stats[13], Vvb = s_stats[14];
        const float cscale = rsqrtf((float)HDIM) * LOG2E;

        int h = t >> 6, m = t & 63;
        float p = s_pooled[m];
        float rk = rsqrtf(p * p * Vkw + 2.0f * p * Ckwb + Vkb + LN_EPS);
        float rv = rsqrtf(p * p * Vvw + 2.0f * p * Cvwb + Vvb + LN_EPS);

        float a1 = 0.f, a2 = 0.f, a3 = 0.f, w = 0.f;
        #pragma unroll 8
        for (int j = 0; j < HDIM; j++) {
            int e = h * HDIM + j;
            float4 kk = s_k[e];
            float4 vv = s_v[e];
            float4 qq = s_q[e];
            float ke = ((kk.x - mkw) * p + (kk.y - mkb)) * rk * kk.z + kk.w;
            float ve = ((vv.x - mvw) * p + (vv.y - mvb)) * rv * vv.z + vv.w;
            float uq = (qq.x - mqw) * qq.z;
            float tq = (qq.y - mqb) * qq.z;
            a1 = fmaf(uq, ke, a1);
            a2 = fmaf(tq, ke, a2);
            a3 = fmaf(qq.w, ke, a3);
            w  = fmaf(ve, s_ow[e], w);
        }
        float4 out4 = make_float4(a1 * cscale, a2 * cscale, a3 * cscale, w);
        sAB[t] = out4;
        if (tb == 0) g_AB[t] = out4;
    }
    __syncthreads();

    // G-table: 4 threads/node (one head each), shfl-combine, gate folded
    const float hstep = (XMAX - XMIN) / (float)(TABN - 1);
    float ob  = outb[0];
    float gw0 = __ldg(gatew)     * -LOG2E;
    float gw1 = __ldg(gatew + 1) * -LOG2E;
    float gbv = __ldg(gateb)     * -LOG2E;
    int node = tb * 64 + (t >> 2);       // 16 blocks * 64 = 1024
    int hh   = t & 3;
    float x  = XMIN + (float)node * hstep;
    float r  = rsqrtf(fmaf(x, fmaf(qa, x, qb2), qc));
    float part = eval_head(x, r, sAB + (hh << 6));
    part += __shfl_xor_sync(0xffffffffu, part, 1);
    part += __shfl_xor_sync(0xffffffffu, part, 2);
    if (hh == 0) {
        float F = part + ob;
        float z = fmaf(gw1, F, fmaf(gw0, x, gbv));
        float g = __fdividef(1.0f, 1.0f + fast_ex2(z));
        float G = fmaf(g, F - x, x);
        g_G2[node].x = G;
        if (node > 0) g_G2[node - 1].y = G;
    }
}

// =========== kernel 3: apply (direct gather, L1-resident 8KB table) ===========
__global__ __launch_bounds__(APPLY_TPB) void apply_kernel(
    const float* __restrict__ coeff, float* __restrict__ out,
    const float* __restrict__ gatew, const float* __restrict__ gateb,
    const float* __restrict__ outb)
{
    int tid = blockIdx.x * APPLY_TPB + threadIdx.x;   // one float4 each, exact
    const float4* cin = reinterpret_cast<const float4*>(coeff);
    float4* cout = reinterpret_cast<float4*>(out);
    float gw0 = __ldg(gatew)     * -LOG2E;
    float gw1 = __ldg(gatew + 1) * -LOG2E;
    float gbv = __ldg(gateb)     * -LOG2E;
    float ob  = __ldg(outb);

    const float INVH = (float)(TABN - 1) / (XMAX - XMIN);
    const float BIAS = -XMIN * INVH;

    float4 xv = cin[tid];
    float xin[4] = {xv.x, xv.y, xv.z, xv.w};

    // issue all 4 table gathers up front (independent -> MLP)
    float2 p[4];
    float fpos[4];
    bool inr[4];
    #pragma unroll
    for (int j = 0; j < 4; j++) {
        float x = xin[j];
        inr[j] = (x >= XMIN) && (x <= XMAX);
        float tpos = fmaf(x, INVH, BIAS);
        int q0 = __float2int_rd(tpos);
        q0 = (q0 < 0) ? 0 : ((q0 > TABN - 2) ? TABN - 2 : q0);
        fpos[j] = tpos - (float)q0;
        p[j] = g_G2[q0];
    }

    float res[4];
    #pragma unroll
    for (int j = 0; j < 4; j++) {
        float x = xin[j];
        res[j] = inr[j] ? fmaf(fpos[j], p[j].y - p[j].x, p[j].x)
                        : eval_G_cold(x, gw0, gw1, gbv, ob);
    }
    cout[tid] = make_float4(res[0], res[1], res[2], res[3]);
}

// ---------------- launch ----------------
extern "C" void kernel_launch(void* const* d_in, const int* in_sizes, int n_in,
                              void* d_out, int out_size) {
    (void)in_sizes; (void)n_in; (void)out_size;
    const float* coeff = (const float*)d_in[0];
    const float* proto = (const float*)d_in[1];
    const float* qw    = (const float*)d_in[2];
    const float* qb    = (const float*)d_in[3];
    const float* qg    = (const float*)d_in[4];
    const float* qbeta = (const float*)d_in[5];
    const float* kw    = (const float*)d_in[6];
    const float* kb    = (const float*)d_in[7];
    const float* kg    = (const float*)d_in[8];
    const float* kbeta = (const float*)d_in[9];
    const float* vw    = (const float*)d_in[10];
    const float* vb    = (const float*)d_in[11];
    const float* vg    = (const float*)d_in[12];
    const float* vbeta = (const float*)d_in[13];
    const float* outw  = (const float*)d_in[14];
    const float* outb  = (const float*)d_in[15];
    const float* gatew = (const float*)d_in[16];
    const float* gateb = (const float*)d_in[17];
    float* out = (float*)d_out;

    pool_kernel<<<POOL_BLOCKS, POOL_TPB>>>(proto);
    table_kernel<<<TAB_BLOCKS, TAB_TPB>>>(qw, qb, qg, qbeta, kw, kb, kg, kbeta,
                                          vw, vb, vg, vbeta, outw, outb,
                                          gatew, gateb);
    apply_kernel<<<APPLY_BLOCKS, APPLY_TPB>>>(coeff, out, gatew, gateb, outb);
}